// round 14
// baseline (speedup 1.0000x reference)
#include <cuda_runtime.h>
#include <cuda_bf16.h>
#include <cstdint>

// yoloLoss: pred/target [B=4096, S=14, S=14, 30] fp32 -> scalar loss.
// Persistent blocks (456), double-buffered cp.async staging, per-thread cell
// math (cell preloaded via vectorized LDS.64), per-thread double accumulator,
// block reduce -> atomicAdd(g_acc). Finalize kernel writes out + resets g_acc.
//
// CRITICAL (proven r7): the IoU chain feeding argmax uses non-contractible
// IEEE intrinsics in the reference's exact op order. Degenerate (clamped)
// boxes make iou a +/-1ulp residue around 0; FMA contraction flips argmax
// decisions vs XLA -> 1.4e-3 error. DO NOT TOUCH.

#define SDIM 14
#define CPB 128                  // cells per tile
#define NTHREADS 128
#define TILE_F4 960              // float4 per array per tile (128*30/4)
#define TILE_BYTES 15360         // bytes per array per tile
#define BUF_BYTES 30720          // pred+target per buffer
#define SMEM_BYTES (2*BUF_BYTES + 64)
#define MAX_GRID 456             // 152 SMs * 3 blocks

__device__ double g_acc;   // static-init 0; finalize re-zeros after each use

__global__ void finalize_kernel(float* out, int n, double inv_batch) {
    if (threadIdx.x == 0) {
        double v = g_acc;
        float r = (float)(v * inv_batch);
        for (int i = 0; i < n; i++) out[i] = r;
        g_acc = 0.0;     // self-reset for next graph replay
    }
}

__device__ __forceinline__ float smooth_l1(float d) {
    float ad = fabsf(d);
    return ad < 1.0f ? 0.5f * d * d : ad - 0.5f;
}

__device__ __forceinline__ float sqrt_approx(float x) {
    float r;
    asm("sqrt.approx.f32 %0, %1;" : "=f"(r) : "f"(x));
    return r;
}

__device__ __forceinline__ void cp_async16(uint32_t dst, const void* src) {
    asm volatile("cp.async.cg.shared.global [%0], [%1], 16;" :: "r"(dst), "l"(src));
}
#define CP_COMMIT() asm volatile("cp.async.commit_group;" ::: "memory")
#define CP_WAIT0()  asm volatile("cp.async.wait_group 0;" ::: "memory")
#define CP_WAIT1()  asm volatile("cp.async.wait_group 1;" ::: "memory")

// Stage one tile (pred then target, contiguous) into buffer via cp.async.
__device__ __forceinline__ void stage_tile(
    const float* __restrict__ pred, const float* __restrict__ target,
    int tile, uint32_t dst_base, int tid, long long total4)
{
    const float4* srcp = reinterpret_cast<const float4*>(pred) + (long long)tile * TILE_F4;
    const float4* srct = reinterpret_cast<const float4*>(target) + (long long)tile * TILE_F4;
    long long rem = total4 - (long long)tile * TILE_F4;           // remaining f4 per array
    const int n4 = (rem < TILE_F4) ? (int)rem : TILE_F4;
    #pragma unroll
    for (int k = 0; k < 15; k++) {
        int idx = tid + k * NTHREADS;          // 0..1919 over [pred | target]
        int a = idx - TILE_F4;                 // index into target half
        if (idx < n4) {
            cp_async16(dst_base + idx * 16, srcp + idx);
        } else if (a >= 0 && a < n4) {
            cp_async16(dst_base + idx * 16, srct + a);
        }
    }
}

__device__ __forceinline__ float cell_loss(const float* __restrict__ psm,
                                           const float* __restrict__ tsm,
                                           int cell)
{
    // Preload the whole cell with vectorized LDS.64 (base is 8B-aligned:
    // tid*120 bytes). Halves LDS instruction count + conflict wavefronts
    // vs scalar loads.
    float p[30], t[30];
    {
        const float2* p2 = reinterpret_cast<const float2*>(psm);
        const float2* t2 = reinterpret_cast<const float2*>(tsm);
        #pragma unroll
        for (int i = 0; i < 15; i++) {
            float2 a = p2[i]; p[2*i] = a.x; p[2*i+1] = a.y;
            float2 b = t2[i]; t[2*i] = b.x; t[2*i+1] = b.y;
        }
    }

    const int cell_in_img = cell % (SDIM * SDIM);
    const float gi = (float)(cell_in_img % SDIM);   // varies along axis 2
    const float gj = (float)(cell_in_img / SDIM);   // varies along axis 1
    const float STEPF = 1.0f / 14.0f;               // f32-rounded 1/14, same as XLA

    // IoU of pred box k vs target box k, bit-exact to XLA op-by-op.
    float iou[2];
    #pragma unroll
    for (int k = 0; k < 2; k++) {
        const float pbx = p[5*k+0], pby = p[5*k+1], pbw = p[5*k+2], pbh = p[5*k+3];
        const float tbx = t[5*k+0], tby = t[5*k+1], tbw = t[5*k+2], tbh = t[5*k+3];

        float px = fmaxf(__fsub_rn(__fmul_rn(__fadd_rn(pbx, gi), STEPF),
                                   __fmul_rn(pbw, 0.5f)), 0.0f);
        float py = fmaxf(__fsub_rn(__fmul_rn(__fadd_rn(pby, gj), STEPF),
                                   __fmul_rn(pbh, 0.5f)), 0.0f);
        float pw = fmaxf(pbw, 0.0f);
        float ph = fmaxf(pbh, 0.0f);
        float tx = fmaxf(__fsub_rn(__fmul_rn(__fadd_rn(tbx, gi), STEPF),
                                   __fmul_rn(tbw, 0.5f)), 0.0f);
        float ty = fmaxf(__fsub_rn(__fmul_rn(__fadd_rn(tby, gj), STEPF),
                                   __fmul_rn(tbh, 0.5f)), 0.0f);
        float tw = fmaxf(tbw, 0.0f);
        float th = fmaxf(tbh, 0.0f);

        float iw = fmaxf(__fsub_rn(__fadd_rn(pw, tw),
                                   __fsub_rn(fmaxf(__fadd_rn(px, pw), __fadd_rn(tx, tw)),
                                             fminf(px, tx))), 0.0f);
        float ih = fmaxf(__fsub_rn(__fadd_rn(ph, th),
                                   __fsub_rn(fmaxf(__fadd_rn(py, ph), __fadd_rn(ty, th)),
                                             fminf(py, ty))), 0.0f);
        float inter = __fmul_rn(iw, ih);
        float uni = __fsub_rn(__fadd_rn(__fmul_rn(pw, ph), __fmul_rn(tw, th)), inter);
        iou[k] = __fdiv_rn(inter, __fadd_rn(uni, 1e-6f));
    }

    const bool ob0 = t[4] > 0.0f;
    const bool ob1 = t[9] > 0.0f;
    const bool sig = ob1;                         // sig_mask = obj_mask[..., 1]
    const int max_i = (iou[1] > iou[0]) ? 1 : 0;  // argmax: first max wins
    const bool om0 = sig ? (ob0 && (max_i == 0)) : ob0;
    const bool om1 = sig ? (max_i == 1) : ob1;    // ob1 is true when sig

    // Confidence terms
    float d0 = p[4] - t[4]; d0 *= d0;
    float d1 = p[9] - t[9]; d1 *= d1;
    float obj_loss   = (om0 ? d0 : 0.0f) + (om1 ? d1 : 0.0f);
    float noobj_loss = (om0 ? 0.0f : d0) + (om1 ? 0.0f : d1);

    // Coord terms (smooth-L1 on raw xy; on sqrt(max(wh,1e-6))). sqrt.approx:
    // value-only (never feeds a mask), err ~1e-7 rel.
    float coord = 0.0f;
    if (om0) {
        coord += smooth_l1(p[0] - t[0]) + smooth_l1(p[1] - t[1]);
        coord += smooth_l1(sqrt_approx(fmaxf(p[2], 1e-6f)) - sqrt_approx(fmaxf(t[2], 1e-6f)));
        coord += smooth_l1(sqrt_approx(fmaxf(p[3], 1e-6f)) - sqrt_approx(fmaxf(t[3], 1e-6f)));
    }
    if (om1) {
        coord += smooth_l1(p[5] - t[5]) + smooth_l1(p[6] - t[6]);
        coord += smooth_l1(sqrt_approx(fmaxf(p[7], 1e-6f)) - sqrt_approx(fmaxf(t[7], 1e-6f)));
        coord += smooth_l1(sqrt_approx(fmaxf(p[8], 1e-6f)) - sqrt_approx(fmaxf(t[8], 1e-6f)));
    }

    // Class loss: NLL of log_softmax over 20 classes at argmax(target_cls).
    // Tree-shaped reductions (depth 5), mask-exact argmax (strict '>').
    float cls = 0.0f;
    if (sig) {
        float mx[20];
        #pragma unroll
        for (int c = 0; c < 20; c++) mx[c] = p[10 + c];
        #pragma unroll
        for (int n = 20; n > 1; n = (n + 1) / 2) {
            #pragma unroll
            for (int c = 0; c < 10; c++) {
                if (c < n / 2) mx[c] = fmaxf(mx[2*c], mx[2*c+1]);
                else if (2*c == n - 1) mx[c] = mx[n - 1];
            }
        }
        const float m = mx[0];

        float sv[20];
        #pragma unroll
        for (int c = 0; c < 20; c++) sv[c] = __expf(p[10 + c] - m);
        #pragma unroll
        for (int n = 20; n > 1; n = (n + 1) / 2) {
            #pragma unroll
            for (int c = 0; c < 10; c++) {
                if (c < n / 2) sv[c] = sv[2*c] + sv[2*c+1];
                else if (2*c == n - 1) sv[c] = sv[n - 1];
            }
        }
        const float s = sv[0];

        float av[20]; int ai[20];
        #pragma unroll
        for (int c = 0; c < 20; c++) { av[c] = t[10 + c]; ai[c] = c; }
        #pragma unroll
        for (int n = 20; n > 1; n = (n + 1) / 2) {
            #pragma unroll
            for (int c = 0; c < 10; c++) {
                if (c < n / 2) {
                    bool g = av[2*c+1] > av[2*c];
                    av[c] = g ? av[2*c+1] : av[2*c];
                    ai[c] = g ? ai[2*c+1] : ai[2*c];
                } else if (2*c == n - 1) { av[c] = av[n - 1]; ai[c] = ai[n - 1]; }
            }
        }
        cls = m + __logf(s) - p[10 + ai[0]];
    }

    return 3.0f * coord + obj_loss + 0.3f * noobj_loss + 1.5f * cls;
}

__global__ void __launch_bounds__(NTHREADS, 3) yolo_loss_kernel(
    const float* __restrict__ pred,
    const float* __restrict__ target,
    int n_cells)
{
    extern __shared__ float smem[];                 // [buf0 p|t][buf1 p|t][warp_sums]
    double* warp_sums = reinterpret_cast<double*>(smem + 2 * (BUF_BYTES / 4));
    uint32_t smem_u32 = (uint32_t)__cvta_generic_to_shared(smem);

    const int tid = threadIdx.x;
    const int ntiles = (n_cells + CPB - 1) / CPB;
    const int stride = gridDim.x;
    const long long total4 = (long long)n_cells * 30 / 4;

    double acc = 0.0;
    int tile = blockIdx.x;
    int ibuf = 0;

    if (tile < ntiles)
        stage_tile(pred, target, tile, smem_u32, tid, total4);
    CP_COMMIT();

    while (tile < ntiles) {
        const int next = tile + stride;
        if (next < ntiles) {
            stage_tile(pred, target, next, smem_u32 + (ibuf ^ 1) * BUF_BYTES, tid, total4);
            CP_COMMIT();
            CP_WAIT1();                 // current tile's group done
        } else {
            CP_WAIT0();
        }
        __syncthreads();

        const float* base = smem + ibuf * (BUF_BYTES / 4);
        const int cell = tile * CPB + tid;
        if (cell < n_cells)
            acc += (double)cell_loss(base + tid * 30, base + (TILE_BYTES / 4) + tid * 30, cell);

        __syncthreads();                // buffer free before overwrite next iter
        tile = next;
        ibuf ^= 1;
    }

    // Block reduction in double: warp shuffle, then cross-warp via SMEM.
    #pragma unroll
    for (int off = 16; off > 0; off >>= 1)
        acc += __shfl_down_sync(0xFFFFFFFFu, acc, off);
    if ((tid & 31) == 0) warp_sums[tid >> 5] = acc;
    __syncthreads();
    if (tid == 0) {
        double s = warp_sums[0];
        #pragma unroll
        for (int w = 1; w < NTHREADS / 32; w++) s += warp_sums[w];
        atomicAdd(&g_acc, s);
    }
}

extern "C" void kernel_launch(void* const* d_in, const int* in_sizes, int n_in,
                              void* d_out, int out_size) {
    const float* pred   = (const float*)d_in[0];
    const float* target = (const float*)d_in[1];
    float* out = (float*)d_out;

    const int n_cells = in_sizes[0] / 30;
    const int batch = n_cells / (SDIM * SDIM);
    const double inv_batch = 1.0 / (double)batch;
    const int ntiles = (n_cells + CPB - 1) / CPB;
    const int blocks = (ntiles < MAX_GRID) ? ntiles : MAX_GRID;

    cudaFuncSetAttribute(yolo_loss_kernel,
                         cudaFuncAttributeMaxDynamicSharedMemorySize, SMEM_BYTES);
    yolo_loss_kernel<<<blocks, NTHREADS, SMEM_BYTES>>>(pred, target, n_cells);
    finalize_kernel<<<1, 32>>>(out, out_size, inv_batch);
}

// round 16
// speedup vs baseline: 1.5272x; 1.5272x over previous
#include <cuda_runtime.h>
#include <cuda_bf16.h>
#include <cstdint>

// yoloLoss: pred/target [B=4096, S=14, S=14, 30] fp32 -> scalar loss.
// Persistent blocks (456), double-buffered cp.async staging, per-thread cell
// math (on-demand LDS reads — preloading spills!), per-thread double
// accumulator, block reduce -> atomicAdd(g_acc). Finalize kernel (PDL,
// launch overlapped with main) writes out + resets g_acc.
//
// CRITICAL (proven r7): the IoU chain feeding argmax uses non-contractible
// IEEE intrinsics in the reference's exact op order. Degenerate (clamped)
// boxes make iou a +/-1ulp residue around 0; FMA contraction flips argmax
// decisions vs XLA -> 1.4e-3 error. DO NOT TOUCH.
//
// r14 lesson: do NOT preload the 60-float cell into registers — blows the
// ~94-reg budget at 12 warps/SM and spills to local. Keep on-demand LDS.

#define SDIM 14
#define CPB 128                  // cells per tile
#define NTHREADS 128
#define TILE_F4 960              // float4 per array per tile (128*30/4)
#define TILE_BYTES 15360         // bytes per array per tile
#define BUF_BYTES 30720          // pred+target per buffer
#define SMEM_BYTES (2*BUF_BYTES + 64)
#define MAX_GRID 456             // 152 SMs * 3 blocks

__device__ double g_acc;   // static-init 0; finalize re-zeros after each use

__global__ void finalize_kernel(float* out, int n, double inv_batch) {
    // PDL: launched early (overlapped with main); wait for primary grid
    // completion + memory visibility before reading g_acc.
    cudaGridDependencySynchronize();
    if (threadIdx.x == 0) {
        double v = g_acc;
        float r = (float)(v * inv_batch);
        for (int i = 0; i < n; i++) out[i] = r;
        g_acc = 0.0;     // self-reset for next graph replay
    }
}

__device__ __forceinline__ float smooth_l1(float d) {
    float ad = fabsf(d);
    return ad < 1.0f ? 0.5f * d * d : ad - 0.5f;
}

__device__ __forceinline__ float sqrt_approx(float x) {
    float r;
    asm("sqrt.approx.f32 %0, %1;" : "=f"(r) : "f"(x));
    return r;
}

__device__ __forceinline__ void cp_async16(uint32_t dst, const void* src) {
    asm volatile("cp.async.cg.shared.global [%0], [%1], 16;" :: "r"(dst), "l"(src));
}
#define CP_COMMIT() asm volatile("cp.async.commit_group;" ::: "memory")
#define CP_WAIT0()  asm volatile("cp.async.wait_group 0;" ::: "memory")
#define CP_WAIT1()  asm volatile("cp.async.wait_group 1;" ::: "memory")

// Stage one tile (pred then target, contiguous) into buffer via cp.async.
__device__ __forceinline__ void stage_tile(
    const float* __restrict__ pred, const float* __restrict__ target,
    int tile, uint32_t dst_base, int tid, long long total4)
{
    const float4* srcp = reinterpret_cast<const float4*>(pred) + (long long)tile * TILE_F4;
    const float4* srct = reinterpret_cast<const float4*>(target) + (long long)tile * TILE_F4;
    long long rem = total4 - (long long)tile * TILE_F4;           // remaining f4 per array
    const int n4 = (rem < TILE_F4) ? (int)rem : TILE_F4;
    #pragma unroll
    for (int k = 0; k < 15; k++) {
        int idx = tid + k * NTHREADS;          // 0..1919 over [pred | target]
        int a = idx - TILE_F4;                 // index into target half
        if (idx < n4) {
            cp_async16(dst_base + idx * 16, srcp + idx);
        } else if (a >= 0 && a < n4) {
            cp_async16(dst_base + idx * 16, srct + a);
        }
    }
}

__device__ __forceinline__ float cell_loss(const float* __restrict__ p,
                                           const float* __restrict__ t,
                                           int cell)
{
    const int cell_in_img = cell % (SDIM * SDIM);
    const float gi = (float)(cell_in_img % SDIM);   // varies along axis 2
    const float gj = (float)(cell_in_img / SDIM);   // varies along axis 1
    const float STEPF = 1.0f / 14.0f;               // f32-rounded 1/14, same as XLA

    // IoU of pred box k vs target box k, bit-exact to XLA op-by-op.
    float iou[2];
    #pragma unroll
    for (int k = 0; k < 2; k++) {
        const float pbx = p[5*k+0], pby = p[5*k+1], pbw = p[5*k+2], pbh = p[5*k+3];
        const float tbx = t[5*k+0], tby = t[5*k+1], tbw = t[5*k+2], tbh = t[5*k+3];

        float px = fmaxf(__fsub_rn(__fmul_rn(__fadd_rn(pbx, gi), STEPF),
                                   __fmul_rn(pbw, 0.5f)), 0.0f);
        float py = fmaxf(__fsub_rn(__fmul_rn(__fadd_rn(pby, gj), STEPF),
                                   __fmul_rn(pbh, 0.5f)), 0.0f);
        float pw = fmaxf(pbw, 0.0f);
        float ph = fmaxf(pbh, 0.0f);
        float tx = fmaxf(__fsub_rn(__fmul_rn(__fadd_rn(tbx, gi), STEPF),
                                   __fmul_rn(tbw, 0.5f)), 0.0f);
        float ty = fmaxf(__fsub_rn(__fmul_rn(__fadd_rn(tby, gj), STEPF),
                                   __fmul_rn(tbh, 0.5f)), 0.0f);
        float tw = fmaxf(tbw, 0.0f);
        float th = fmaxf(tbh, 0.0f);

        float iw = fmaxf(__fsub_rn(__fadd_rn(pw, tw),
                                   __fsub_rn(fmaxf(__fadd_rn(px, pw), __fadd_rn(tx, tw)),
                                             fminf(px, tx))), 0.0f);
        float ih = fmaxf(__fsub_rn(__fadd_rn(ph, th),
                                   __fsub_rn(fmaxf(__fadd_rn(py, ph), __fadd_rn(ty, th)),
                                             fminf(py, ty))), 0.0f);
        float inter = __fmul_rn(iw, ih);
        float uni = __fsub_rn(__fadd_rn(__fmul_rn(pw, ph), __fmul_rn(tw, th)), inter);
        iou[k] = __fdiv_rn(inter, __fadd_rn(uni, 1e-6f));
    }

    const bool ob0 = t[4] > 0.0f;
    const bool ob1 = t[9] > 0.0f;
    const bool sig = ob1;                         // sig_mask = obj_mask[..., 1]
    const int max_i = (iou[1] > iou[0]) ? 1 : 0;  // argmax: first max wins
    const bool om0 = sig ? (ob0 && (max_i == 0)) : ob0;
    const bool om1 = sig ? (max_i == 1) : ob1;    // ob1 is true when sig

    // Confidence terms
    float d0 = p[4] - t[4]; d0 *= d0;
    float d1 = p[9] - t[9]; d1 *= d1;
    float obj_loss   = (om0 ? d0 : 0.0f) + (om1 ? d1 : 0.0f);
    float noobj_loss = (om0 ? 0.0f : d0) + (om1 ? 0.0f : d1);

    // Coord terms (smooth-L1 on raw xy; on sqrt(max(wh,1e-6))). sqrt.approx:
    // value-only (never feeds a mask), err ~1e-7 rel.
    float coord = 0.0f;
    if (om0) {
        coord += smooth_l1(p[0] - t[0]) + smooth_l1(p[1] - t[1]);
        coord += smooth_l1(sqrt_approx(fmaxf(p[2], 1e-6f)) - sqrt_approx(fmaxf(t[2], 1e-6f)));
        coord += smooth_l1(sqrt_approx(fmaxf(p[3], 1e-6f)) - sqrt_approx(fmaxf(t[3], 1e-6f)));
    }
    if (om1) {
        coord += smooth_l1(p[5] - t[5]) + smooth_l1(p[6] - t[6]);
        coord += smooth_l1(sqrt_approx(fmaxf(p[7], 1e-6f)) - sqrt_approx(fmaxf(t[7], 1e-6f)));
        coord += smooth_l1(sqrt_approx(fmaxf(p[8], 1e-6f)) - sqrt_approx(fmaxf(t[8], 1e-6f)));
    }

    // Class loss: NLL of log_softmax over 20 classes at argmax(target_cls).
    // Tree-shaped reductions (depth 5), mask-exact argmax (strict '>').
    float cls = 0.0f;
    if (sig) {
        float pv[20], tv[20];
        #pragma unroll
        for (int c = 0; c < 20; c++) { pv[c] = p[10 + c]; tv[c] = t[10 + c]; }

        float mx[20];
        #pragma unroll
        for (int c = 0; c < 20; c++) mx[c] = pv[c];
        #pragma unroll
        for (int n = 20; n > 1; n = (n + 1) / 2) {
            #pragma unroll
            for (int c = 0; c < 10; c++) {
                if (c < n / 2) mx[c] = fmaxf(mx[2*c], mx[2*c+1]);
                else if (2*c == n - 1) mx[c] = mx[n - 1];
            }
        }
        const float m = mx[0];

        float sv[20];
        #pragma unroll
        for (int c = 0; c < 20; c++) sv[c] = __expf(pv[c] - m);
        #pragma unroll
        for (int n = 20; n > 1; n = (n + 1) / 2) {
            #pragma unroll
            for (int c = 0; c < 10; c++) {
                if (c < n / 2) sv[c] = sv[2*c] + sv[2*c+1];
                else if (2*c == n - 1) sv[c] = sv[n - 1];
            }
        }
        const float s = sv[0];

        float av[20]; int ai[20];
        #pragma unroll
        for (int c = 0; c < 20; c++) { av[c] = tv[c]; ai[c] = c; }
        #pragma unroll
        for (int n = 20; n > 1; n = (n + 1) / 2) {
            #pragma unroll
            for (int c = 0; c < 10; c++) {
                if (c < n / 2) {
                    bool g = av[2*c+1] > av[2*c];
                    av[c] = g ? av[2*c+1] : av[2*c];
                    ai[c] = g ? ai[2*c+1] : ai[2*c];
                } else if (2*c == n - 1) { av[c] = av[n - 1]; ai[c] = ai[n - 1]; }
            }
        }
        cls = m + __logf(s) - pv[ai[0]];
    }

    return 3.0f * coord + obj_loss + 0.3f * noobj_loss + 1.5f * cls;
}

__global__ void __launch_bounds__(NTHREADS, 3) yolo_loss_kernel(
    const float* __restrict__ pred,
    const float* __restrict__ target,
    int n_cells)
{
    // PDL: allow the dependent finalize kernel to launch immediately; its
    // grid-dependency sync still waits for this grid's completion.
    cudaTriggerProgrammaticLaunchCompletion();

    extern __shared__ float smem[];                 // [buf0 p|t][buf1 p|t][warp_sums]
    double* warp_sums = reinterpret_cast<double*>(smem + 2 * (BUF_BYTES / 4));
    uint32_t smem_u32 = (uint32_t)__cvta_generic_to_shared(smem);

    const int tid = threadIdx.x;
    const int ntiles = (n_cells + CPB - 1) / CPB;
    const int stride = gridDim.x;
    const long long total4 = (long long)n_cells * 30 / 4;

    double acc = 0.0;
    int tile = blockIdx.x;
    int ibuf = 0;

    if (tile < ntiles)
        stage_tile(pred, target, tile, smem_u32, tid, total4);
    CP_COMMIT();

    while (tile < ntiles) {
        const int next = tile + stride;
        if (next < ntiles) {
            stage_tile(pred, target, next, smem_u32 + (ibuf ^ 1) * BUF_BYTES, tid, total4);
            CP_COMMIT();
            CP_WAIT1();                 // current tile's group done
        } else {
            CP_WAIT0();
        }
        __syncthreads();

        const float* base = smem + ibuf * (BUF_BYTES / 4);
        const int cell = tile * CPB + tid;
        if (cell < n_cells)
            acc += (double)cell_loss(base + tid * 30, base + (TILE_BYTES / 4) + tid * 30, cell);

        __syncthreads();                // buffer free before overwrite next iter
        tile = next;
        ibuf ^= 1;
    }

    // Block reduction in double: warp shuffle, then cross-warp via SMEM.
    #pragma unroll
    for (int off = 16; off > 0; off >>= 1)
        acc += __shfl_down_sync(0xFFFFFFFFu, acc, off);
    if ((tid & 31) == 0) warp_sums[tid >> 5] = acc;
    __syncthreads();
    if (tid == 0) {
        double s = warp_sums[0];
        #pragma unroll
        for (int w = 1; w < NTHREADS / 32; w++) s += warp_sums[w];
        atomicAdd(&g_acc, s);
    }
}

extern "C" void kernel_launch(void* const* d_in, const int* in_sizes, int n_in,
                              void* d_out, int out_size) {
    const float* pred   = (const float*)d_in[0];
    const float* target = (const float*)d_in[1];
    float* out = (float*)d_out;

    const int n_cells = in_sizes[0] / 30;
    const int batch = n_cells / (SDIM * SDIM);
    const double inv_batch = 1.0 / (double)batch;
    const int ntiles = (n_cells + CPB - 1) / CPB;
    const int blocks = (ntiles < MAX_GRID) ? ntiles : MAX_GRID;

    cudaFuncSetAttribute(yolo_loss_kernel,
                         cudaFuncAttributeMaxDynamicSharedMemorySize, SMEM_BYTES);
    yolo_loss_kernel<<<blocks, NTHREADS, SMEM_BYTES>>>(pred, target, n_cells);

    // Finalize via PDL: launch overlaps the main kernel; device-side
    // cudaGridDependencySynchronize() orders the read of g_acc.
    cudaLaunchConfig_t cfg = {};
    cfg.gridDim = dim3(1, 1, 1);
    cfg.blockDim = dim3(32, 1, 1);
    cfg.dynamicSmemBytes = 0;
    cfg.stream = 0;
    cudaLaunchAttribute attrs[1];
    attrs[0].id = cudaLaunchAttributeProgrammaticStreamSerialization;
    attrs[0].val.programmaticStreamSerializationAllowed = 1;
    cfg.attrs = attrs;
    cfg.numAttrs = 1;
    cudaLaunchKernelEx(&cfg, finalize_kernel, out, out_size, inv_batch);
}